// round 10
// baseline (speedup 1.0000x reference)
#include <cuda_runtime.h>
#include <cuda_bf16.h>
#include <cstdint>

#define NROWS 50000
#define MPAD  50048            // 391 * 128
#define NFEAT 512
#define HID   128
#define NEDGE 1600000
#define NCHUNK 4
#define BLKCH 98               // row-blocks per chunk (last: 391-294=97)

// ------------------------- scratch (device globals) -------------------------
__device__ float g_xw[(size_t)NROWS * HID];
__device__ __nv_bfloat16 g_bh1[HID * NFEAT];    // W1^T hi  [128, 512]
__device__ __nv_bfloat16 g_bl1[HID * NFEAT];
__device__ __nv_bfloat16 g_bh2[NFEAT * HID];    // W2^T hi  [512, 128]
__device__ __nv_bfloat16 g_bl2[NFEAT * HID];
__device__ __align__(16) int2 g_e1[NEDGE];      // packed (col, val) per edge
__device__ __align__(16) int2 g_e2[NEDGE];
__device__ int   g_rs1[NROWS + 1];
__device__ int   g_rs2[NROWS + 1];
__device__ int   g_cnt[2 * NROWS];
__device__ int   g_next[2 * NROWS];

// --------------------------- CSR build -----------------------------------
__global__ void k_zero2(int* p) {
    int i = blockIdx.x * blockDim.x + threadIdx.x;
    if (i < 2 * NROWS) p[i] = 0;
}

__global__ void k_hist2(const int* __restrict__ r1, const int* __restrict__ r2,
                        int* __restrict__ cnt) {
    long i = (long)blockIdx.x * blockDim.x + threadIdx.x;
    if (i < NEDGE)               atomicAdd(&cnt[r1[i]], 1);
    else if (i < 2L * NEDGE)     atomicAdd(&cnt[NROWS + r2[i - NEDGE]], 1);
}

// 2 blocks; block g scans cnt[g*NROWS..] -> rs_g (and next copy)
__global__ __launch_bounds__(1024) void k_scan2(const int* __restrict__ cnt,
                                                int* __restrict__ rs1,
                                                int* __restrict__ rs2,
                                                int* __restrict__ next) {
    __shared__ int wsum[32];
    __shared__ int carry;
    const int g = blockIdx.x;
    const int* c = cnt + g * NROWS;
    int* rs = g ? rs2 : rs1;
    int* nx = next + g * NROWS;
    const int lane = threadIdx.x & 31;
    const int warp = threadIdx.x >> 5;
    if (threadIdx.x == 0) carry = 0;
    __syncthreads();
    for (int base = 0; base < NROWS; base += 1024) {
        int i = base + (int)threadIdx.x;
        int v = (i < NROWS) ? c[i] : 0;
        int s = v;
        #pragma unroll
        for (int o = 1; o < 32; o <<= 1) {
            int t = __shfl_up_sync(0xffffffffu, s, o);
            if (lane >= o) s += t;
        }
        if (lane == 31) wsum[warp] = s;
        __syncthreads();
        if (warp == 0) {
            int ws = wsum[lane];
            #pragma unroll
            for (int o = 1; o < 32; o <<= 1) {
                int t = __shfl_up_sync(0xffffffffu, ws, o);
                if (lane >= o) ws += t;
            }
            wsum[lane] = ws;
        }
        __syncthreads();
        int excl = carry + (warp ? wsum[warp - 1] : 0) + s - v;
        if (i < NROWS) { rs[i] = excl; nx[i] = excl; }
        __syncthreads();
        if (threadIdx.x == 0) carry += wsum[31];
        __syncthreads();
    }
    if (threadIdx.x == 0) rs[NROWS] = carry;
}

// single-graph scatter (next offset selects counter bank)
__global__ void k_scatter1(const int* __restrict__ r, const int* __restrict__ c,
                           const float* __restrict__ v, int* __restrict__ next,
                           int2* __restrict__ e) {
    int i = blockIdx.x * blockDim.x + threadIdx.x;
    if (i < NEDGE) {
        int p = atomicAdd(&next[r[i]], 1);
        e[p] = make_int2(c[i], __float_as_int(v[i]));
    }
}

// --------------------- W split+transpose: W[K,N] -> Bh/Bl [N,K] --------------
__global__ void k_splitw2(const float* __restrict__ W, __nv_bfloat16* __restrict__ bh,
                          __nv_bfloat16* __restrict__ bl, int K, int N) {
    int i = blockIdx.x * blockDim.x + threadIdx.x;
    if (i >= K * N) return;
    int k = i / N, n = i % N;
    float a = W[i];
    __nv_bfloat16 h = __float2bfloat16(a);
    bh[(size_t)n * K + k] = h;
    bl[(size_t)n * K + k] = __float2bfloat16(a - __bfloat162float(h));
}

// ----------------- fused-split mma.sync bf16 GEMM (R5/R7-proven) --------------
// C[M,Nc] fp32 = A[M,K] fp32 @ (Bh+Bl)[Nc,K]^T with in-kernel A hi/lo split.
// rbOff: row-block offset (row chunking for the SPMM2->GEMM2 pipeline).
#define BK 32
#define SROW2 80                      // 32 bf16 (64B) + 16B pad: conflict-free ldmatrix
#define TILE2 (128 * SROW2)           // 10240
#define GSMEM2 (8 * TILE2)            // 81920: AH0 AH1 AL0 AL1 BH0 BH1 BL0 BL1

__device__ __forceinline__ uint32_t smem_u32(const void* p) {
    uint32_t a;
    asm("{ .reg .u64 t; cvta.to.shared.u64 t, %1; cvt.u32.u64 %0, t; }" : "=r"(a) : "l"(p));
    return a;
}
__device__ __forceinline__ void cpa16(uint32_t s, const void* g) {
    asm volatile("cp.async.cg.shared.global [%0], [%1], 16;" :: "r"(s), "l"(g));
}
__device__ __forceinline__ void ldm_x4(uint32_t* r, uint32_t a) {
    asm volatile("ldmatrix.sync.aligned.m8n8.x4.shared.b16 {%0,%1,%2,%3}, [%4];"
                 : "=r"(r[0]), "=r"(r[1]), "=r"(r[2]), "=r"(r[3]) : "r"(a));
}
__device__ __forceinline__ void ldm_x2(uint32_t* r, uint32_t a) {
    asm volatile("ldmatrix.sync.aligned.m8n8.x2.shared.b16 {%0,%1}, [%2];"
                 : "=r"(r[0]), "=r"(r[1]) : "r"(a));
}
__device__ __forceinline__ void mma16816(float* d, const uint32_t* a, const uint32_t* b) {
    asm volatile("mma.sync.aligned.m16n8k16.row.col.f32.bf16.bf16.f32 "
                 "{%0,%1,%2,%3}, {%4,%5,%6,%7}, {%8,%9}, {%0,%1,%2,%3};"
                 : "+f"(d[0]), "+f"(d[1]), "+f"(d[2]), "+f"(d[3])
                 : "r"(a[0]), "r"(a[1]), "r"(a[2]), "r"(a[3]), "r"(b[0]), "r"(b[1]));
}
__device__ __forceinline__ uint32_t pack_bf2(float x, float y) {
    __nv_bfloat162 t(__float2bfloat16(x), __float2bfloat16(y));
    return *(uint32_t*)&t;
}

template <bool EPI>
__global__ void __launch_bounds__(256, 2) k_gemm_f(
    const float* __restrict__ A, const __nv_bfloat16* __restrict__ Bh,
    const __nv_bfloat16* __restrict__ Bl, float* __restrict__ C,
    int M, int Nc, int K, const float* __restrict__ bias, int rbOff) {
    extern __shared__ char sm[];
    const uint32_t s0 = smem_u32(sm);
    const uint32_t sAH0 = s0,              sAH1 = s0 + TILE2;
    const uint32_t sAL0 = s0 + 2 * TILE2,  sAL1 = s0 + 3 * TILE2;
    const uint32_t sBH0 = s0 + 4 * TILE2,  sBH1 = s0 + 5 * TILE2;
    const uint32_t sBL0 = s0 + 6 * TILE2,  sBL1 = s0 + 7 * TILE2;

    const int tid  = threadIdx.x;
    const int lane = tid & 31;
    const int wid  = tid >> 5;
    const int warpM = wid & 1;
    const int warpN = wid >> 1;
    const int rowBase = (blockIdx.x + rbOff) * 128;
    const int colBase = blockIdx.y * 128;

    const int ar  = tid >> 3;
    const int ac4 = tid & 7;
    const int br = tid >> 1;
    const int b0 = (tid & 1) * 16;
    const char* gBh = (const char*)(Bh + (size_t)(colBase + br) * K);
    const char* gBl = (const char*)(Bl + (size_t)(colBase + br) * K);
    const uint32_t bDst = br * SROW2 + b0;

    const int nIter = K / BK;

    float4 ra[4];
    #pragma unroll
    for (int p = 0; p < 4; p++) {
        int row = rowBase + ar + p * 32;
        ra[p] = (row < M) ? *(const float4*)(A + (size_t)row * K + ac4 * 4)
                          : make_float4(0.f, 0.f, 0.f, 0.f);
    }
    cpa16(sBH0 + bDst,      gBh + b0);
    cpa16(sBH0 + bDst + 32, gBh + b0 + 32);
    cpa16(sBL0 + bDst,      gBl + b0);
    cpa16(sBL0 + bDst + 32, gBl + b0 + 32);
    asm volatile("cp.async.commit_group;");

    const int aRow = (lane & 7) + ((lane >> 3) & 1) * 8;
    const int aK   = ((lane >> 4) & 1) * 8;
    const int bRow = lane & 7;
    const int bK   = ((lane >> 3) & 1) * 8;
    const uint32_t aOff = (warpM * 64 + aRow) * SROW2 + aK * 2;
    const uint32_t bOff = (warpN * 32 + bRow) * SROW2 + bK * 2;

    float acc[4][4][4];
    #pragma unroll
    for (int i = 0; i < 4; i++)
        #pragma unroll
        for (int j = 0; j < 4; j++)
            #pragma unroll
            for (int q = 0; q < 4; q++) acc[i][j][q] = 0.f;

    for (int it = 0; it < nIter; it++) {
        const int cur = it & 1;
        const uint32_t aH = cur ? sAH1 : sAH0;
        const uint32_t aL = cur ? sAL1 : sAL0;
        const uint32_t bH = cur ? sBH1 : sBH0;
        const uint32_t bL = cur ? sBL1 : sBL0;

        #pragma unroll
        for (int p = 0; p < 4; p++) {
            float4 v = ra[p];
            uint32_t h01 = pack_bf2(v.x, v.y);
            uint32_t h23 = pack_bf2(v.z, v.w);
            float hx = __bfloat162float(__float2bfloat16(v.x));
            float hy = __bfloat162float(__float2bfloat16(v.y));
            float hz = __bfloat162float(__float2bfloat16(v.z));
            float hw = __bfloat162float(__float2bfloat16(v.w));
            uint32_t l01 = pack_bf2(v.x - hx, v.y - hy);
            uint32_t l23 = pack_bf2(v.z - hz, v.w - hw);
            uint32_t dst = (uint32_t)(ar + p * 32) * SROW2 + ac4 * 8;
            asm volatile("st.shared.v2.b32 [%0], {%1,%2};" :: "r"(aH + dst), "r"(h01), "r"(h23));
            asm volatile("st.shared.v2.b32 [%0], {%1,%2};" :: "r"(aL + dst), "r"(l01), "r"(l23));
        }

        if (it + 1 < nIter) {
            const uint32_t nBH = cur ? sBH0 : sBH1;
            const uint32_t nBL = cur ? sBL0 : sBL1;
            const size_t ko = (size_t)(it + 1) * 64;      // 32 bf16 = 64 bytes
            cpa16(nBH + bDst,      gBh + ko + b0);
            cpa16(nBH + bDst + 32, gBh + ko + b0 + 32);
            cpa16(nBL + bDst,      gBl + ko + b0);
            cpa16(nBL + bDst + 32, gBl + ko + b0 + 32);
            asm volatile("cp.async.commit_group;");
            const int kf = (it + 1) * 32 + ac4 * 4;
            #pragma unroll
            for (int p = 0; p < 4; p++) {
                int row = rowBase + ar + p * 32;
                ra[p] = (row < M) ? *(const float4*)(A + (size_t)row * K + kf)
                                  : make_float4(0.f, 0.f, 0.f, 0.f);
            }
            asm volatile("cp.async.wait_group 1;");
        } else {
            asm volatile("cp.async.wait_group 0;");
        }
        __syncthreads();

        #pragma unroll
        for (int kb = 0; kb < 2; kb++) {
            uint32_t bfH[4][2], bfL[4][2];
            #pragma unroll
            for (int j = 0; j < 4; j++) {
                ldm_x2(bfH[j], bH + bOff + j * 8 * SROW2 + kb * 32);
                ldm_x2(bfL[j], bL + bOff + j * 8 * SROW2 + kb * 32);
            }
            #pragma unroll
            for (int i = 0; i < 4; i++) {
                uint32_t afH[4], afL[4];
                ldm_x4(afH, aH + aOff + i * 16 * SROW2 + kb * 32);
                ldm_x4(afL, aL + aOff + i * 16 * SROW2 + kb * 32);
                #pragma unroll
                for (int j = 0; j < 4; j++) {
                    mma16816(acc[i][j], afH, bfH[j]);
                    mma16816(acc[i][j], afH, bfL[j]);
                    mma16816(acc[i][j], afL, bfH[j]);
                }
            }
        }
        __syncthreads();
    }

    #pragma unroll
    for (int i = 0; i < 4; i++) {
        int r0 = rowBase + warpM * 64 + i * 16 + (lane >> 2);
        #pragma unroll
        for (int j = 0; j < 4; j++) {
            int c0 = colBase + warpN * 32 + j * 8 + (lane & 3) * 2;
            float2 v0 = make_float2(acc[i][j][0], acc[i][j][1]);
            float2 v1 = make_float2(acc[i][j][2], acc[i][j][3]);
            if (EPI) {
                float2 b = *(const float2*)(bias + c0);
                v0.x = fmaxf(v0.x + b.x, 0.f); v0.y = fmaxf(v0.y + b.y, 0.f);
                v1.x = fmaxf(v1.x + b.x, 0.f); v1.y = fmaxf(v1.y + b.y, 0.f);
            }
            if (r0 < M)     *(float2*)(C + (size_t)r0 * Nc + c0)       = v0;
            if (r0 + 8 < M) *(float2*)(C + (size_t)(r0 + 8) * Nc + c0) = v1;
        }
    }
}

// ------------------------------ SPMM (D=128) --------------------------------
// warp per row in [rowBeg, rowEnd)
template <bool EPI>
__global__ __launch_bounds__(256) void k_spmm_d128(
    const int* __restrict__ rs, const int2* __restrict__ ev,
    const float* __restrict__ dense, const float* __restrict__ bias,
    float* __restrict__ out, int rowBeg, int rowEnd) {
    int row = rowBeg + ((blockIdx.x * blockDim.x + threadIdx.x) >> 5);
    int lane = threadIdx.x & 31;
    if (row >= rowEnd) return;
    int s = rs[row], e = rs[row + 1];
    float4 acc = make_float4(0.f, 0.f, 0.f, 0.f);
    for (int i = s; i < e; i++) {
        int2 p = __ldg(&ev[i]);
        float v = __int_as_float(p.y);
        float4 d = ((const float4*)(dense + (size_t)p.x * HID))[lane];
        acc.x = fmaf(v, d.x, acc.x);
        acc.y = fmaf(v, d.y, acc.y);
        acc.z = fmaf(v, d.z, acc.z);
        acc.w = fmaf(v, d.w, acc.w);
    }
    if (EPI) {
        float4 b = ((const float4*)bias)[lane];
        acc.x = fmaxf(acc.x + b.x, 0.f);
        acc.y = fmaxf(acc.y + b.y, 0.f);
        acc.z = fmaxf(acc.z + b.z, 0.f);
        acc.w = fmaxf(acc.w + b.w, 0.f);
    }
    ((float4*)(out + (size_t)row * HID))[lane] = acc;
}

// ------------------------------ launch --------------------------------------
extern "C" void kernel_launch(void* const* d_in, const int* in_sizes, int n_in,
                              void* d_out, int out_size) {
    const float* x           = (const float*)d_in[0];
    const int*   adj_row     = (const int*)d_in[1];
    const int*   adj_col     = (const int*)d_in[2];
    const float* adj_val     = (const float*)d_in[3];
    const int*   adj_inv_row = (const int*)d_in[4];
    const int*   adj_inv_col = (const int*)d_in[5];
    const float* adj_inv_val = (const float*)d_in[6];
    const float* W1          = (const float*)d_in[7];
    const float* b1          = (const float*)d_in[8];
    const float* W2          = (const float*)d_in[9];
    const float* b2          = (const float*)d_in[10];

    float* out = (float*)d_out;                   // [N, NFEAT]
    float* h   = out + (size_t)NROWS * NFEAT;     // [N, HID]

    float* xw;
    __nv_bfloat16 *bh1, *bl1, *bh2, *bl2;
    int2 *e1, *e2;
    int *rs1, *rs2, *cnt, *next;
    cudaGetSymbolAddress((void**)&xw,   g_xw);
    cudaGetSymbolAddress((void**)&bh1,  g_bh1);
    cudaGetSymbolAddress((void**)&bl1,  g_bl1);
    cudaGetSymbolAddress((void**)&bh2,  g_bh2);
    cudaGetSymbolAddress((void**)&bl2,  g_bl2);
    cudaGetSymbolAddress((void**)&e1,   g_e1);
    cudaGetSymbolAddress((void**)&e2,   g_e2);
    cudaGetSymbolAddress((void**)&rs1,  g_rs1);
    cudaGetSymbolAddress((void**)&rs2,  g_rs2);
    cudaGetSymbolAddress((void**)&cnt,  g_cnt);
    cudaGetSymbolAddress((void**)&next, g_next);

    cudaFuncSetAttribute(k_gemm_f<false>,
                         cudaFuncAttributeMaxDynamicSharedMemorySize, GSMEM2);
    cudaFuncSetAttribute(k_gemm_f<true>,
                         cudaFuncAttributeMaxDynamicSharedMemorySize, GSMEM2);

    // one-time side stream + events (no device memory involved)
    static cudaStream_t sSide = nullptr;
    static cudaEvent_t evFork = nullptr, evScan = nullptr, evG1 = nullptr, evS2 = nullptr;
    static cudaEvent_t evC[NCHUNK] = {};
    static cudaEvent_t evDone = nullptr;
    if (!sSide) {
        cudaStreamCreateWithFlags(&sSide, cudaStreamNonBlocking);
        cudaEventCreateWithFlags(&evFork, cudaEventDisableTiming);
        cudaEventCreateWithFlags(&evScan, cudaEventDisableTiming);
        cudaEventCreateWithFlags(&evG1,   cudaEventDisableTiming);
        cudaEventCreateWithFlags(&evS2,   cudaEventDisableTiming);
        for (int c = 0; c < NCHUNK; c++)
            cudaEventCreateWithFlags(&evC[c], cudaEventDisableTiming);
        cudaEventCreateWithFlags(&evDone, cudaEventDisableTiming);
    }

    const int TB = 256;
    const int g2N = (2 * NROWS + TB - 1) / TB;
    const int gE  = (NEDGE + TB - 1) / TB;

    // ---- fork ----
    cudaEventRecord(evFork, 0);
    cudaStreamWaitEvent(sSide, evFork, 0);

    // side stream: weight splits + GEMM1 (independent of CSR)
    k_splitw2<<<(NFEAT * HID + TB - 1) / TB, TB, 0, sSide>>>(W1, bh1, bl1, NFEAT, HID);
    k_splitw2<<<(HID * NFEAT + TB - 1) / TB, TB, 0, sSide>>>(W2, bh2, bl2, HID, NFEAT);
    {
        dim3 grid(MPAD / 128, HID / 128);
        k_gemm_f<false><<<grid, 256, GSMEM2, sSide>>>(x, bh1, bl1, xw,
                                                      NROWS, HID, NFEAT, nullptr, 0);
    }
    cudaEventRecord(evG1, sSide);

    // main stream: CSR common phase + graph-1 scatter only
    k_zero2<<<g2N, TB>>>(cnt);
    k_hist2<<<(int)((2L * NEDGE + TB - 1) / TB), TB>>>(adj_row, adj_inv_row, cnt);
    k_scan2<<<2, 1024>>>(cnt, rs1, rs2, next);
    cudaEventRecord(evScan, 0);
    k_scatter1<<<gE, TB>>>(adj_row, adj_col, adj_val, next, e1);

    // side stream: graph-2 scatter (after scan + GEMM1) overlaps SPMM1
    cudaStreamWaitEvent(sSide, evScan, 0);
    k_scatter1<<<gE, TB, 0, sSide>>>(adj_inv_row, adj_inv_col, adj_inv_val,
                                     next + NROWS, e2);
    cudaEventRecord(evS2, sSide);

    // main: SPMM1 needs xw (side GEMM1) + rs1/e1 (main)
    cudaStreamWaitEvent(0, evG1, 0);
    k_spmm_d128<true><<<(NROWS * 32 + TB - 1) / TB, TB>>>(rs1, e1, xw, b1, h,
                                                          0, NROWS);

    // ---- chunked SPMM2 -> GEMM2 pipeline ----
    cudaStreamWaitEvent(0, evS2, 0);    // SPMM2 needs e2
    for (int c = 0; c < NCHUNK; c++) {
        int rb0 = c * BLKCH;
        int rb1 = (c == NCHUNK - 1) ? (MPAD / 128) : (rb0 + BLKCH);
        int row0 = rb0 * 128;
        int row1 = rb1 * 128; if (row1 > NROWS) row1 = NROWS;
        int nrows = row1 - row0;
        // main: SPMM2 chunk (writes xw rows [row0,row1))
        k_spmm_d128<false><<<(nrows * 32 + TB - 1) / TB, TB>>>(rs2, e2, h,
                                                               nullptr, xw,
                                                               row0, row1);
        cudaEventRecord(evC[c], 0);
        // side: GEMM2 chunk (reads xw rows of this chunk only)
        cudaStreamWaitEvent(sSide, evC[c], 0);
        dim3 grid(rb1 - rb0, NFEAT / 128);
        k_gemm_f<true><<<grid, 256, GSMEM2, sSide>>>(xw, bh2, bl2, out,
                                                     NROWS, NFEAT, HID, b2, rb0);
    }
    cudaEventRecord(evDone, sSide);
    cudaStreamWaitEvent(0, evDone, 0);  // join before capture ends
}

// round 11
// speedup vs baseline: 1.0637x; 1.0637x over previous
#include <cuda_runtime.h>
#include <cuda_bf16.h>
#include <cuda_fp16.h>
#include <cstdint>

#define NROWS 50000
#define MPAD  50048            // 391 * 128
#define NFEAT 512
#define HID   128
#define NEDGE 1600000

// ------------------------- scratch (device globals) -------------------------
__device__ float g_xw[(size_t)NROWS * HID];
__device__ __half g_h16[(size_t)NROWS * HID];   // fp16 copy of h for SPMM2 gather
__device__ __nv_bfloat16 g_bh1[HID * NFEAT];    // W1^T hi  [128, 512]
__device__ __nv_bfloat16 g_bl1[HID * NFEAT];
__device__ __nv_bfloat16 g_bh2[NFEAT * HID];    // W2^T hi  [512, 128]
__device__ __nv_bfloat16 g_bl2[NFEAT * HID];
__device__ __align__(16) int2 g_e1[NEDGE];      // packed (col, val) per edge
__device__ __align__(16) int2 g_e2[NEDGE];
__device__ int   g_rs1[NROWS + 1];
__device__ int   g_rs2[NROWS + 1];
__device__ int   g_cnt[2 * NROWS];
__device__ int   g_next[2 * NROWS];

// --------------------------- CSR build -----------------------------------
__global__ void k_zero2(int* p) {
    int i = blockIdx.x * blockDim.x + threadIdx.x;
    if (i < 2 * NROWS) p[i] = 0;
}

__global__ void k_hist2(const int* __restrict__ r1, const int* __restrict__ r2,
                        int* __restrict__ cnt) {
    long i = (long)blockIdx.x * blockDim.x + threadIdx.x;
    if (i < NEDGE)               atomicAdd(&cnt[r1[i]], 1);
    else if (i < 2L * NEDGE)     atomicAdd(&cnt[NROWS + r2[i - NEDGE]], 1);
}

// 2 blocks; block g scans cnt[g*NROWS..] -> rs_g (and next copy)
__global__ __launch_bounds__(1024) void k_scan2(const int* __restrict__ cnt,
                                                int* __restrict__ rs1,
                                                int* __restrict__ rs2,
                                                int* __restrict__ next) {
    __shared__ int wsum[32];
    __shared__ int carry;
    const int g = blockIdx.x;
    const int* c = cnt + g * NROWS;
    int* rs = g ? rs2 : rs1;
    int* nx = next + g * NROWS;
    const int lane = threadIdx.x & 31;
    const int warp = threadIdx.x >> 5;
    if (threadIdx.x == 0) carry = 0;
    __syncthreads();
    for (int base = 0; base < NROWS; base += 1024) {
        int i = base + (int)threadIdx.x;
        int v = (i < NROWS) ? c[i] : 0;
        int s = v;
        #pragma unroll
        for (int o = 1; o < 32; o <<= 1) {
            int t = __shfl_up_sync(0xffffffffu, s, o);
            if (lane >= o) s += t;
        }
        if (lane == 31) wsum[warp] = s;
        __syncthreads();
        if (warp == 0) {
            int ws = wsum[lane];
            #pragma unroll
            for (int o = 1; o < 32; o <<= 1) {
                int t = __shfl_up_sync(0xffffffffu, ws, o);
                if (lane >= o) ws += t;
            }
            wsum[lane] = ws;
        }
        __syncthreads();
        int excl = carry + (warp ? wsum[warp - 1] : 0) + s - v;
        if (i < NROWS) { rs[i] = excl; nx[i] = excl; }
        __syncthreads();
        if (threadIdx.x == 0) carry += wsum[31];
        __syncthreads();
    }
    if (threadIdx.x == 0) rs[NROWS] = carry;
}

// single-graph scatter (next offset selects counter bank)
__global__ void k_scatter1(const int* __restrict__ r, const int* __restrict__ c,
                           const float* __restrict__ v, int* __restrict__ next,
                           int2* __restrict__ e) {
    int i = blockIdx.x * blockDim.x + threadIdx.x;
    if (i < NEDGE) {
        int p = atomicAdd(&next[r[i]], 1);
        e[p] = make_int2(c[i], __float_as_int(v[i]));
    }
}

// --------------------- W split+transpose: W[K,N] -> Bh/Bl [N,K] --------------
__global__ void k_splitw2(const float* __restrict__ W, __nv_bfloat16* __restrict__ bh,
                          __nv_bfloat16* __restrict__ bl, int K, int N) {
    int i = blockIdx.x * blockDim.x + threadIdx.x;
    if (i >= K * N) return;
    int k = i / N, n = i % N;
    float a = W[i];
    __nv_bfloat16 h = __float2bfloat16(a);
    bh[(size_t)n * K + k] = h;
    bl[(size_t)n * K + k] = __float2bfloat16(a - __bfloat162float(h));
}

// ----------------- fused-split mma.sync bf16 GEMM (R5/R7-proven) --------------
// C[M,Nc] fp32 = A[M,K] fp32 @ (Bh+Bl)[Nc,K]^T with in-kernel A hi/lo split.
#define BK 32
#define SROW2 80                      // 32 bf16 (64B) + 16B pad: conflict-free ldmatrix
#define TILE2 (128 * SROW2)           // 10240
#define GSMEM2 (8 * TILE2)            // 81920: AH0 AH1 AL0 AL1 BH0 BH1 BL0 BL1

__device__ __forceinline__ uint32_t smem_u32(const void* p) {
    uint32_t a;
    asm("{ .reg .u64 t; cvta.to.shared.u64 t, %1; cvt.u32.u64 %0, t; }" : "=r"(a) : "l"(p));
    return a;
}
__device__ __forceinline__ void cpa16(uint32_t s, const void* g) {
    asm volatile("cp.async.cg.shared.global [%0], [%1], 16;" :: "r"(s), "l"(g));
}
__device__ __forceinline__ void ldm_x4(uint32_t* r, uint32_t a) {
    asm volatile("ldmatrix.sync.aligned.m8n8.x4.shared.b16 {%0,%1,%2,%3}, [%4];"
                 : "=r"(r[0]), "=r"(r[1]), "=r"(r[2]), "=r"(r[3]) : "r"(a));
}
__device__ __forceinline__ void ldm_x2(uint32_t* r, uint32_t a) {
    asm volatile("ldmatrix.sync.aligned.m8n8.x2.shared.b16 {%0,%1}, [%2];"
                 : "=r"(r[0]), "=r"(r[1]) : "r"(a));
}
__device__ __forceinline__ void mma16816(float* d, const uint32_t* a, const uint32_t* b) {
    asm volatile("mma.sync.aligned.m16n8k16.row.col.f32.bf16.bf16.f32 "
                 "{%0,%1,%2,%3}, {%4,%5,%6,%7}, {%8,%9}, {%0,%1,%2,%3};"
                 : "+f"(d[0]), "+f"(d[1]), "+f"(d[2]), "+f"(d[3])
                 : "r"(a[0]), "r"(a[1]), "r"(a[2]), "r"(a[3]), "r"(b[0]), "r"(b[1]));
}
__device__ __forceinline__ uint32_t pack_bf2(float x, float y) {
    __nv_bfloat162 t(__float2bfloat16(x), __float2bfloat16(y));
    return *(uint32_t*)&t;
}

template <bool EPI>
__global__ void __launch_bounds__(256, 2) k_gemm_f(
    const float* __restrict__ A, const __nv_bfloat16* __restrict__ Bh,
    const __nv_bfloat16* __restrict__ Bl, float* __restrict__ C,
    int M, int Nc, int K, const float* __restrict__ bias) {
    extern __shared__ char sm[];
    const uint32_t s0 = smem_u32(sm);
    const uint32_t sAH0 = s0,              sAH1 = s0 + TILE2;
    const uint32_t sAL0 = s0 + 2 * TILE2,  sAL1 = s0 + 3 * TILE2;
    const uint32_t sBH0 = s0 + 4 * TILE2,  sBH1 = s0 + 5 * TILE2;
    const uint32_t sBL0 = s0 + 6 * TILE2,  sBL1 = s0 + 7 * TILE2;

    const int tid  = threadIdx.x;
    const int lane = tid & 31;
    const int wid  = tid >> 5;
    const int warpM = wid & 1;
    const int warpN = wid >> 1;
    const int rowBase = blockIdx.x * 128;
    const int colBase = blockIdx.y * 128;

    const int ar  = tid >> 3;
    const int ac4 = tid & 7;
    const int br = tid >> 1;
    const int b0 = (tid & 1) * 16;
    const char* gBh = (const char*)(Bh + (size_t)(colBase + br) * K);
    const char* gBl = (const char*)(Bl + (size_t)(colBase + br) * K);
    const uint32_t bDst = br * SROW2 + b0;

    const int nIter = K / BK;

    float4 ra[4];
    #pragma unroll
    for (int p = 0; p < 4; p++) {
        int row = rowBase + ar + p * 32;
        ra[p] = (row < M) ? *(const float4*)(A + (size_t)row * K + ac4 * 4)
                          : make_float4(0.f, 0.f, 0.f, 0.f);
    }
    cpa16(sBH0 + bDst,      gBh + b0);
    cpa16(sBH0 + bDst + 32, gBh + b0 + 32);
    cpa16(sBL0 + bDst,      gBl + b0);
    cpa16(sBL0 + bDst + 32, gBl + b0 + 32);
    asm volatile("cp.async.commit_group;");

    const int aRow = (lane & 7) + ((lane >> 3) & 1) * 8;
    const int aK   = ((lane >> 4) & 1) * 8;
    const int bRow = lane & 7;
    const int bK   = ((lane >> 3) & 1) * 8;
    const uint32_t aOff = (warpM * 64 + aRow) * SROW2 + aK * 2;
    const uint32_t bOff = (warpN * 32 + bRow) * SROW2 + bK * 2;

    float acc[4][4][4];
    #pragma unroll
    for (int i = 0; i < 4; i++)
        #pragma unroll
        for (int j = 0; j < 4; j++)
            #pragma unroll
            for (int q = 0; q < 4; q++) acc[i][j][q] = 0.f;

    for (int it = 0; it < nIter; it++) {
        const int cur = it & 1;
        const uint32_t aH = cur ? sAH1 : sAH0;
        const uint32_t aL = cur ? sAL1 : sAL0;
        const uint32_t bH = cur ? sBH1 : sBH0;
        const uint32_t bL = cur ? sBL1 : sBL0;

        #pragma unroll
        for (int p = 0; p < 4; p++) {
            float4 v = ra[p];
            uint32_t h01 = pack_bf2(v.x, v.y);
            uint32_t h23 = pack_bf2(v.z, v.w);
            float hx = __bfloat162float(__float2bfloat16(v.x));
            float hy = __bfloat162float(__float2bfloat16(v.y));
            float hz = __bfloat162float(__float2bfloat16(v.z));
            float hw = __bfloat162float(__float2bfloat16(v.w));
            uint32_t l01 = pack_bf2(v.x - hx, v.y - hy);
            uint32_t l23 = pack_bf2(v.z - hz, v.w - hw);
            uint32_t dst = (uint32_t)(ar + p * 32) * SROW2 + ac4 * 8;
            asm volatile("st.shared.v2.b32 [%0], {%1,%2};" :: "r"(aH + dst), "r"(h01), "r"(h23));
            asm volatile("st.shared.v2.b32 [%0], {%1,%2};" :: "r"(aL + dst), "r"(l01), "r"(l23));
        }

        if (it + 1 < nIter) {
            const uint32_t nBH = cur ? sBH0 : sBH1;
            const uint32_t nBL = cur ? sBL0 : sBL1;
            const size_t ko = (size_t)(it + 1) * 64;      // 32 bf16 = 64 bytes
            cpa16(nBH + bDst,      gBh + ko + b0);
            cpa16(nBH + bDst + 32, gBh + ko + b0 + 32);
            cpa16(nBL + bDst,      gBl + ko + b0);
            cpa16(nBL + bDst + 32, gBl + ko + b0 + 32);
            asm volatile("cp.async.commit_group;");
            const int kf = (it + 1) * 32 + ac4 * 4;
            #pragma unroll
            for (int p = 0; p < 4; p++) {
                int row = rowBase + ar + p * 32;
                ra[p] = (row < M) ? *(const float4*)(A + (size_t)row * K + kf)
                                  : make_float4(0.f, 0.f, 0.f, 0.f);
            }
            asm volatile("cp.async.wait_group 1;");
        } else {
            asm volatile("cp.async.wait_group 0;");
        }
        __syncthreads();

        #pragma unroll
        for (int kb = 0; kb < 2; kb++) {
            uint32_t bfH[4][2], bfL[4][2];
            #pragma unroll
            for (int j = 0; j < 4; j++) {
                ldm_x2(bfH[j], bH + bOff + j * 8 * SROW2 + kb * 32);
                ldm_x2(bfL[j], bL + bOff + j * 8 * SROW2 + kb * 32);
            }
            #pragma unroll
            for (int i = 0; i < 4; i++) {
                uint32_t afH[4], afL[4];
                ldm_x4(afH, aH + aOff + i * 16 * SROW2 + kb * 32);
                ldm_x4(afL, aL + aOff + i * 16 * SROW2 + kb * 32);
                #pragma unroll
                for (int j = 0; j < 4; j++) {
                    mma16816(acc[i][j], afH, bfH[j]);
                    mma16816(acc[i][j], afH, bfL[j]);
                    mma16816(acc[i][j], afL, bfH[j]);
                }
            }
        }
        __syncthreads();
    }

    #pragma unroll
    for (int i = 0; i < 4; i++) {
        int r0 = rowBase + warpM * 64 + i * 16 + (lane >> 2);
        #pragma unroll
        for (int j = 0; j < 4; j++) {
            int c0 = colBase + warpN * 32 + j * 8 + (lane & 3) * 2;
            float2 v0 = make_float2(acc[i][j][0], acc[i][j][1]);
            float2 v1 = make_float2(acc[i][j][2], acc[i][j][3]);
            if (EPI) {
                float2 b = *(const float2*)(bias + c0);
                v0.x = fmaxf(v0.x + b.x, 0.f); v0.y = fmaxf(v0.y + b.y, 0.f);
                v1.x = fmaxf(v1.x + b.x, 0.f); v1.y = fmaxf(v1.y + b.y, 0.f);
            }
            if (r0 < M)     *(float2*)(C + (size_t)r0 * Nc + c0)       = v0;
            if (r0 + 8 < M) *(float2*)(C + (size_t)(r0 + 8) * Nc + c0) = v1;
        }
    }
}

// ------------------------------ SPMM (D=128) --------------------------------
// SPMM1: fp32 gather, bias+relu, writes fp32 h AND fp16 h16 copy
__global__ __launch_bounds__(256) void k_spmm1(
    const int* __restrict__ rs, const int2* __restrict__ ev,
    const float* __restrict__ dense, const float* __restrict__ bias,
    float* __restrict__ out, __half* __restrict__ out16) {
    int row = (blockIdx.x * blockDim.x + threadIdx.x) >> 5;
    int lane = threadIdx.x & 31;
    if (row >= NROWS) return;
    int s = rs[row], e = rs[row + 1];
    float4 acc = make_float4(0.f, 0.f, 0.f, 0.f);
    for (int i = s; i < e; i++) {
        int2 p = __ldg(&ev[i]);
        float v = __int_as_float(p.y);
        float4 d = ((const float4*)(dense + (size_t)p.x * HID))[lane];
        acc.x = fmaf(v, d.x, acc.x);
        acc.y = fmaf(v, d.y, acc.y);
        acc.z = fmaf(v, d.z, acc.z);
        acc.w = fmaf(v, d.w, acc.w);
    }
    float4 b = ((const float4*)bias)[lane];
    acc.x = fmaxf(acc.x + b.x, 0.f);
    acc.y = fmaxf(acc.y + b.y, 0.f);
    acc.z = fmaxf(acc.z + b.z, 0.f);
    acc.w = fmaxf(acc.w + b.w, 0.f);
    ((float4*)(out + (size_t)row * HID))[lane] = acc;
    __half2 ha = __floats2half2_rn(acc.x, acc.y);
    __half2 hb = __floats2half2_rn(acc.z, acc.w);
    uint2 q = make_uint2(*(uint32_t*)&ha, *(uint32_t*)&hb);
    *(uint2*)(out16 + (size_t)row * HID + lane * 4) = q;
}

// SPMM2: fp16 gather (half traffic), fp32 accumulate, no epilogue
__global__ __launch_bounds__(256) void k_spmm2_f16(
    const int* __restrict__ rs, const int2* __restrict__ ev,
    const __half* __restrict__ dense16, float* __restrict__ out) {
    int row = (blockIdx.x * blockDim.x + threadIdx.x) >> 5;
    int lane = threadIdx.x & 31;
    if (row >= NROWS) return;
    int s = rs[row], e = rs[row + 1];
    float4 acc = make_float4(0.f, 0.f, 0.f, 0.f);
    for (int i = s; i < e; i++) {
        int2 p = __ldg(&ev[i]);
        float v = __int_as_float(p.y);
        uint2 q = *(const uint2*)(dense16 + (size_t)p.x * HID + lane * 4);
        float2 f0 = __half22float2(*(__half2*)&q.x);
        float2 f1 = __half22float2(*(__half2*)&q.y);
        acc.x = fmaf(v, f0.x, acc.x);
        acc.y = fmaf(v, f0.y, acc.y);
        acc.z = fmaf(v, f1.x, acc.z);
        acc.w = fmaf(v, f1.y, acc.w);
    }
    ((float4*)(out + (size_t)row * HID))[lane] = acc;
}

// ------------------------------ launch --------------------------------------
extern "C" void kernel_launch(void* const* d_in, const int* in_sizes, int n_in,
                              void* d_out, int out_size) {
    const float* x           = (const float*)d_in[0];
    const int*   adj_row     = (const int*)d_in[1];
    const int*   adj_col     = (const int*)d_in[2];
    const float* adj_val     = (const float*)d_in[3];
    const int*   adj_inv_row = (const int*)d_in[4];
    const int*   adj_inv_col = (const int*)d_in[5];
    const float* adj_inv_val = (const float*)d_in[6];
    const float* W1          = (const float*)d_in[7];
    const float* b1          = (const float*)d_in[8];
    const float* W2          = (const float*)d_in[9];
    const float* b2          = (const float*)d_in[10];

    float* out = (float*)d_out;                   // [N, NFEAT]
    float* h   = out + (size_t)NROWS * NFEAT;     // [N, HID]

    float* xw;
    __half* h16;
    __nv_bfloat16 *bh1, *bl1, *bh2, *bl2;
    int2 *e1, *e2;
    int *rs1, *rs2, *cnt, *next;
    cudaGetSymbolAddress((void**)&xw,   g_xw);
    cudaGetSymbolAddress((void**)&h16,  g_h16);
    cudaGetSymbolAddress((void**)&bh1,  g_bh1);
    cudaGetSymbolAddress((void**)&bl1,  g_bl1);
    cudaGetSymbolAddress((void**)&bh2,  g_bh2);
    cudaGetSymbolAddress((void**)&bl2,  g_bl2);
    cudaGetSymbolAddress((void**)&e1,   g_e1);
    cudaGetSymbolAddress((void**)&e2,   g_e2);
    cudaGetSymbolAddress((void**)&rs1,  g_rs1);
    cudaGetSymbolAddress((void**)&rs2,  g_rs2);
    cudaGetSymbolAddress((void**)&cnt,  g_cnt);
    cudaGetSymbolAddress((void**)&next, g_next);

    cudaFuncSetAttribute(k_gemm_f<false>,
                         cudaFuncAttributeMaxDynamicSharedMemorySize, GSMEM2);
    cudaFuncSetAttribute(k_gemm_f<true>,
                         cudaFuncAttributeMaxDynamicSharedMemorySize, GSMEM2);

    // one-time side stream + events (no device memory involved)
    static cudaStream_t sSide = nullptr;
    static cudaEvent_t evFork = nullptr, evScan = nullptr, evG1 = nullptr, evS2 = nullptr;
    if (!sSide) {
        cudaStreamCreateWithFlags(&sSide, cudaStreamNonBlocking);
        cudaEventCreateWithFlags(&evFork, cudaEventDisableTiming);
        cudaEventCreateWithFlags(&evScan, cudaEventDisableTiming);
        cudaEventCreateWithFlags(&evG1,   cudaEventDisableTiming);
        cudaEventCreateWithFlags(&evS2,   cudaEventDisableTiming);
    }

    const int TB = 256;
    const int g2N = (2 * NROWS + TB - 1) / TB;
    const int gE  = (NEDGE + TB - 1) / TB;

    // ---- fork ----
    cudaEventRecord(evFork, 0);
    cudaStreamWaitEvent(sSide, evFork, 0);

    // side stream: weight splits + GEMM1 (independent of CSR)
    k_splitw2<<<(NFEAT * HID + TB - 1) / TB, TB, 0, sSide>>>(W1, bh1, bl1, NFEAT, HID);
    k_splitw2<<<(HID * NFEAT + TB - 1) / TB, TB, 0, sSide>>>(W2, bh2, bl2, HID, NFEAT);
    {
        dim3 grid(MPAD / 128, HID / 128);
        k_gemm_f<false><<<grid, 256, GSMEM2, sSide>>>(x, bh1, bl1, xw,
                                                      NROWS, HID, NFEAT, nullptr);
    }
    cudaEventRecord(evG1, sSide);

    // main stream: CSR common phase + graph-1 scatter only
    k_zero2<<<g2N, TB>>>(cnt);
    k_hist2<<<(int)((2L * NEDGE + TB - 1) / TB), TB>>>(adj_row, adj_inv_row, cnt);
    k_scan2<<<2, 1024>>>(cnt, rs1, rs2, next);
    cudaEventRecord(evScan, 0);
    k_scatter1<<<gE, TB>>>(adj_row, adj_col, adj_val, next, e1);

    // side stream: graph-2 scatter (after scan + GEMM1) overlaps SPMM1
    cudaStreamWaitEvent(sSide, evScan, 0);
    k_scatter1<<<gE, TB, 0, sSide>>>(adj_inv_row, adj_inv_col, adj_inv_val,
                                     next + NROWS, e2);
    cudaEventRecord(evS2, sSide);

    // main: SPMM1 needs xw (side GEMM1) + rs1/e1 (main); writes h + h16
    cudaStreamWaitEvent(0, evG1, 0);
    k_spmm1<<<(NROWS * 32 + TB - 1) / TB, TB>>>(rs1, e1, xw, b1, h, h16);

    // main: SPMM2 gathers fp16 h16 (half traffic), writes fp32 g into xw
    cudaStreamWaitEvent(0, evS2, 0);
    k_spmm2_f16<<<(NROWS * 32 + TB - 1) / TB, TB>>>(rs2, e2, h16, xw);

    // GEMM2: out = relu(g @ W2 + b2)
    {
        dim3 grid(MPAD / 128, NFEAT / 128);
        k_gemm_f<true><<<grid, 256, GSMEM2>>>(xw, bh2, bl2, out, NROWS, NFEAT, HID, b2);
    }
}